// round 13
// baseline (speedup 1.0000x reference)
#include <cuda_runtime.h>
#include <cuda_fp16.h>
#include <cstdint>

#define N_NODES 100000
#define E_RAW   300000
#define E_TOT   400000   // raw edges + self loops
#define F1      1024     // heads*hid layer 1
#define HEADS   8
#define F2      128
#define M_TILE  64
#define KC      32       // k chunk for fused GEMM

// ---- scratch (global __device__ arrays; ~49 MB total) ----
__device__ float  g_xagg[(size_t)N_NODES * 32];  // per-node, per-head weighted x sum (normalized)
__device__ __half g_h2h[(size_t)N_NODES * F2];   // layer-2 features per node, fp16 (25.6 MB)
__device__ __half g_W2h[F2 * F1];                // W2 transposed [n][k], fp16
__device__ float  g_as1[N_NODES * HEADS];
__device__ float  g_ad1[N_NODES * HEADS];
__device__ float  g_as2[N_NODES];
__device__ float  g_ad2[N_NODES];
__device__ int    g_deg[N_NODES];                // per-dst degree (then scratch)
__device__ int    g_off[N_NODES + 1];            // CSR offsets
__device__ int    g_cur[N_NODES];                // fill cursors
__device__ int    g_adj[E_TOT];                  // CSR adjacency: src node ids
__device__ float  g_M1s[4 * HEADS];              // W1^T @ a_src  (4 x 8)
__device__ float  g_M1d[4 * HEADS];              // W1^T @ a_dst  (4 x 8)
__device__ int    g_is64;                        // edge_index dtype flag

#define MMA_F16(d, a0, a1, a2, a3, b0, b1) \
    asm volatile("mma.sync.aligned.m16n8k16.row.col.f32.f16.f16.f32 " \
        "{%0,%1,%2,%3}, {%4,%5,%6,%7}, {%8,%9}, {%0,%1,%2,%3};" \
        : "+f"((d)[0]), "+f"((d)[1]), "+f"((d)[2]), "+f"((d)[3]) \
        : "r"(a0), "r"(a1), "r"(a2), "r"(a3), "r"(b0), "r"(b1))

#define LDSM_X4(r, addr) \
    asm volatile("ldmatrix.sync.aligned.m8n8.x4.shared.b16 {%0,%1,%2,%3}, [%4];" \
        : "=r"((r)[0]), "=r"((r)[1]), "=r"((r)[2]), "=r"((r)[3]) : "r"(addr))

__device__ __forceinline__ void decode_edge(const void* ei, int e, int is64,
                                            int& src, int& dst) {
    if (e < E_RAW) {
        if (is64) {
            src = (int)((const long long*)ei)[e];
            dst = (int)((const long long*)ei)[E_RAW + e];
        } else {
            src = ((const int*)ei)[e];
            dst = ((const int*)ei)[E_RAW + e];
        }
    } else {
        src = dst = e - E_RAW;
    }
}

// ------------------------------------------------------------------
// K0: zero degrees; block 0 additionally detects int64 vs int32 layout.
__global__ void k_init(const int* __restrict__ ei32) {
    int i = blockIdx.x * blockDim.x + threadIdx.x;
    if (i < N_NODES) g_deg[i] = 0;
    if (blockIdx.x == 0) {
        int v = ei32[2 * threadIdx.x + 1];
        int any = __syncthreads_or(v);
        if (threadIdx.x == 0) g_is64 = (any == 0) ? 1 : 0;
    }
}

// K1a: count in-degree per dst
__global__ void k_count(const void* __restrict__ ei) {
    int e = blockIdx.x * blockDim.x + threadIdx.x;
    if (e >= E_TOT) return;
    int src, dst;
    decode_edge(ei, e, g_is64, src, dst);
    atomicAdd(&g_deg[dst], 1);
}

// K1b: exclusive scan over degrees (one block, 1024 threads).
__global__ __launch_bounds__(1024) void k_scan() {
    __shared__ int ssum[1024];
    int t = threadIdx.x;
    const int CH = (N_NODES + 1023) / 1024;   // 98
    int start = t * CH;
    int s = 0;
    for (int j = 0; j < CH; ++j) {
        int i = start + j;
        if (i < N_NODES) s += g_deg[i];
    }
    ssum[t] = s;
    __syncthreads();
    // Hillis-Steele inclusive scan, then shift to exclusive
    #pragma unroll
    for (int o = 1; o < 1024; o <<= 1) {
        int v = (t >= o) ? ssum[t - o] : 0;
        __syncthreads();
        ssum[t] += v;
        __syncthreads();
    }
    int run = (t == 0) ? 0 : ssum[t - 1];
    for (int j = 0; j < CH; ++j) {
        int i = start + j;
        if (i < N_NODES) {
            g_off[i] = run;
            g_cur[i] = run;
            run += g_deg[i];
        }
    }
    if (t == 1023) g_off[N_NODES] = run;
}

// K1c: fill CSR adjacency with src node ids
__global__ void k_fill(const void* __restrict__ ei) {
    int e = blockIdx.x * blockDim.x + threadIdx.x;
    if (e >= E_TOT) return;
    int src, dst;
    decode_edge(ei, e, g_is64, src, dst);
    int slot = atomicAdd(&g_cur[dst], 1);
    g_adj[slot] = src;
}

// K1d: pre-convert + transpose W2 -> fp16 [n][k]
__global__ void k_prepW2(const float* __restrict__ W2) {
    int i = blockIdx.x * blockDim.x + threadIdx.x;   // i = n*1024 + k
    if (i < F1 * F2) {
        int n = i >> 10, k = i & 1023;
        g_W2h[i] = __float2half(W2[k * F2 + n]);
    }
}

// ------------------------------------------------------------------
// K2a: M1s[d][h] = sum_c W1[d, h*128+c] * a_src[h, c]   (and M1d with a_dst)
__global__ void k_reduceW(const float* __restrict__ W1,
                          const float* __restrict__ as, const float* __restrict__ ad) {
    int wid = (blockIdx.x * blockDim.x + threadIdx.x) >> 5;  // 0..63
    int lane = threadIdx.x & 31;
    int idx = wid & 31;
    int d = idx >> 3, h = idx & 7;
    const float* a = (wid < 32) ? as : ad;
    const float* wrow = W1 + d * F1 + h * 128;
    const float* arow = a + h * 128;
    float s = 0.f;
    #pragma unroll
    for (int c = 0; c < 4; ++c) s += wrow[lane + 32 * c] * arow[lane + 32 * c];
    #pragma unroll
    for (int o = 16; o; o >>= 1) s += __shfl_xor_sync(0xffffffffu, s, o);
    if (lane == 0) {
        if (wid < 32) g_M1s[d * 8 + h] = s; else g_M1d[d * 8 + h] = s;
    }
}

// K2b: per-node attention scalars: as1[n,h] = sum_d x[n,d] * M1s[d,h]
__global__ __launch_bounds__(256) void k_nodescal(const float* __restrict__ x) {
    int i = blockIdx.x * blockDim.x + threadIdx.x;   // i = n*8 + h
    if (i >= N_NODES * HEADS) return;
    int n = i >> 3, h = i & 7;
    float x0 = x[n * 4 + 0], x1 = x[n * 4 + 1];
    float x2 = x[n * 4 + 2], x3 = x[n * 4 + 3];
    g_as1[i] = x0 * g_M1s[0 * 8 + h] + x1 * g_M1s[1 * 8 + h]
             + x2 * g_M1s[2 * 8 + h] + x3 * g_M1s[3 * 8 + h];
    g_ad1[i] = x0 * g_M1d[0 * 8 + h] + x1 * g_M1d[1 * 8 + h]
             + x2 * g_M1d[2 * 8 + h] + x3 * g_M1d[3 * 8 + h];
}

// ------------------------------------------------------------------
// K3: layer-1 gather in x-space over CSR. Warp per dst node; counted loop
// -> independent per-edge load chains (MLP), no pointer chase.
__global__ __launch_bounds__(256) void k_gather1(const float* __restrict__ x) {
    int i = blockIdx.x * 8 + (threadIdx.x >> 5);
    if (i >= N_NODES) return;
    int lane = threadIdx.x & 31;
    int hh = lane >> 2, dd = lane & 3;

    float adst = (lane < 8) ? g_ad1[i * HEADS + lane] : 0.f;
    float acc = 0.f, denom = 0.f;

    int beg = g_off[i], end = g_off[i + 1];
    for (int j = beg; j < end; ++j) {
        int src = g_adj[j];
        float pp = 0.f;
        if (lane < 8) {
            float tt = g_as1[src * HEADS + lane] + adst;
            tt = (tt > 0.f) ? tt : 0.2f * tt;        // leaky_relu 0.2
            pp = __expf(tt);
        }
        float p = __shfl_sync(0xffffffffu, pp, hh);
        denom += p;
        acc += p * x[src * 4 + dd];
    }
    g_xagg[(size_t)i * 32 + lane] = acc / (denom + 1e-16f);
}

// ------------------------------------------------------------------
// K4: fused layer-1 reconstruct + layer-2 GEMM on fp16 tensor cores.
// (frozen R12 structure: single buffer, cp.async sB, ldmatrix fragments)
__global__ __launch_bounds__(256) void k_fused4(
    const float* __restrict__ W1, const float* __restrict__ b1,
    const float* __restrict__ as2, const float* __restrict__ ad2)
{
    __shared__ __align__(16) __half sA[M_TILE * 40];  // [m][kc] pad 40
    __shared__ __align__(16) __half sB[F2 * 40];      // [n][kc] pad 40
    __shared__ __align__(16) float sxa[M_TILE * 33];  // [m][32] pad 33
    __shared__ float sred[2 * M_TILE];

    int t = threadIdx.x;
    int base = blockIdx.x * M_TILE;
    int lane = t & 31, w = t >> 5;
    int mw = w & 1, nw = w >> 1;
    int g = lane >> 2, t4 = lane & 3;

    #pragma unroll
    for (int q = 0; q < 8; ++q) {
        int idx = q * 256 + t;            // 0..2047
        int m = idx >> 5, col = idx & 31;
        float v = (base + m < N_NODES) ? g_xagg[(size_t)(base + m) * 32 + col] : 0.f;
        sxa[m * 33 + col] = v;
    }
    if (t < 2 * M_TILE) sred[t] = 0.f;
    __syncthreads();

    float acc[2][4][4];
    #pragma unroll
    for (int mf = 0; mf < 2; ++mf)
        #pragma unroll
        for (int nf = 0; nf < 4; ++nf)
            #pragma unroll
            for (int q = 0; q < 4; ++q) acc[mf][nf][q] = 0.f;

    int mp = t >> 2;       // producer node 0..63
    int kq = t & 3;        // producer 8-k chunk

    uint32_t sb_dst[2];
    const __half* sb_src[2];
    #pragma unroll
    for (int q = 0; q < 2; ++q) {
        int lin = q * 256 + t;               // 0..511
        int n = lin >> 2, c8 = lin & 3;
        sb_dst[q] = (uint32_t)__cvta_generic_to_shared(&sB[n * 40 + c8 * 8]);
        sb_src[q] = g_W2h + (size_t)n * F1 + c8 * 8;
    }

    uint32_t sAu = (uint32_t)__cvta_generic_to_shared(&sA[0]);
    uint32_t sBu = (uint32_t)__cvta_generic_to_shared(&sB[0]);
    int a_off = ((lane & 7) + ((lane >> 3) & 1) * 8) * 40 + ((lane >> 4) & 1) * 8;
    int b_off = ((lane & 7) + ((lane >> 3) & 2) * 4) * 40 + ((lane >> 3) & 1) * 8;
    uint32_t am0 = sAu + 2u * (a_off + (mw * 32 + 0) * 40);
    uint32_t am1 = sAu + 2u * (a_off + (mw * 32 + 16) * 40);
    uint32_t bn0 = sBu + 2u * (b_off + (nw * 32 + 0) * 40);
    uint32_t bn2 = sBu + 2u * (b_off + (nw * 32 + 16) * 40);

    for (int c = 0; c < F1 / KC; ++c) {          // 32 chunks
        int h = c >> 2;
        int kg = c * KC;
        #pragma unroll
        for (int q = 0; q < 2; ++q) {
            const __half* src = sb_src[q] + kg;
            asm volatile("cp.async.cg.shared.global [%0], [%1], 16;"
                         :: "r"(sb_dst[q]), "l"(src));
        }
        asm volatile("cp.async.commit_group;");

        float xa0 = sxa[mp * 33 + h * 4 + 0], xa1 = sxa[mp * 33 + h * 4 + 1];
        float xa2 = sxa[mp * 33 + h * 4 + 2], xa3 = sxa[mp * 33 + h * 4 + 3];
        float f[8];
        #pragma unroll
        for (int j2 = 0; j2 < 2; ++j2) {
            int kk = kq * 8 + j2 * 4;
            int cg = kg + kk;
            float4 w0 = *(const float4*)(W1 + 0 * F1 + cg);
            float4 w1 = *(const float4*)(W1 + 1 * F1 + cg);
            float4 w2 = *(const float4*)(W1 + 2 * F1 + cg);
            float4 w3 = *(const float4*)(W1 + 3 * F1 + cg);
            float4 bb = *(const float4*)(b1 + cg);
            f[j2 * 4 + 0] = fmaxf(xa0 * w0.x + xa1 * w1.x + xa2 * w2.x + xa3 * w3.x + bb.x, 0.f);
            f[j2 * 4 + 1] = fmaxf(xa0 * w0.y + xa1 * w1.y + xa2 * w2.y + xa3 * w3.y + bb.y, 0.f);
            f[j2 * 4 + 2] = fmaxf(xa0 * w0.z + xa1 * w1.z + xa2 * w2.z + xa3 * w3.z + bb.z, 0.f);
            f[j2 * 4 + 3] = fmaxf(xa0 * w0.w + xa1 * w1.w + xa2 * w2.w + xa3 * w3.w + bb.w, 0.f);
        }
        uint4 v;
        *(__half2*)&v.x = __floats2half2_rn(f[0], f[1]);
        *(__half2*)&v.y = __floats2half2_rn(f[2], f[3]);
        *(__half2*)&v.z = __floats2half2_rn(f[4], f[5]);
        *(__half2*)&v.w = __floats2half2_rn(f[6], f[7]);
        *(uint4*)(&sA[mp * 40 + kq * 8]) = v;

        asm volatile("cp.async.wait_group 0;" ::: "memory");
        __syncthreads();

        #pragma unroll
        for (int ks = 0; ks < 2; ++ks) {
            uint32_t a0[4], a1[4], b0[4], b2[4];
            LDSM_X4(a0, am0 + ks * 32);
            LDSM_X4(a1, am1 + ks * 32);
            LDSM_X4(b0, bn0 + ks * 32);
            LDSM_X4(b2, bn2 + ks * 32);
            MMA_F16(acc[0][0], a0[0], a0[1], a0[2], a0[3], b0[0], b0[1]);
            MMA_F16(acc[0][1], a0[0], a0[1], a0[2], a0[3], b0[2], b0[3]);
            MMA_F16(acc[0][2], a0[0], a0[1], a0[2], a0[3], b2[0], b2[1]);
            MMA_F16(acc[0][3], a0[0], a0[1], a0[2], a0[3], b2[2], b2[3]);
            MMA_F16(acc[1][0], a1[0], a1[1], a1[2], a1[3], b0[0], b0[1]);
            MMA_F16(acc[1][1], a1[0], a1[1], a1[2], a1[3], b0[2], b0[3]);
            MMA_F16(acc[1][2], a1[0], a1[1], a1[2], a1[3], b2[0], b2[1]);
            MMA_F16(acc[1][3], a1[0], a1[1], a1[2], a1[3], b2[2], b2[3]);
        }
        __syncthreads();
    }

    // ---- epilogue: store h2 (fp16) + fused att2 dots ----
    #pragma unroll
    for (int mf = 0; mf < 2; ++mf) {
        #pragma unroll
        for (int half_ = 0; half_ < 2; ++half_) {
            int mloc = mw * 32 + mf * 16 + g + half_ * 8;
            int node = base + mloc;
            float ps = 0.f, pd = 0.f;
            #pragma unroll
            for (int nf = 0; nf < 4; ++nf) {
                int col = nw * 32 + nf * 8 + 2 * t4;
                float c0 = acc[mf][nf][half_ * 2 + 0];
                float c1 = acc[mf][nf][half_ * 2 + 1];
                if (node < N_NODES) {
                    *(__half2*)(g_h2h + (size_t)node * F2 + col) = __floats2half2_rn(c0, c1);
                }
                ps += c0 * as2[col] + c1 * as2[col + 1];
                pd += c0 * ad2[col] + c1 * ad2[col + 1];
            }
            ps += __shfl_xor_sync(0xffffffffu, ps, 1);
            ps += __shfl_xor_sync(0xffffffffu, ps, 2);
            pd += __shfl_xor_sync(0xffffffffu, pd, 1);
            pd += __shfl_xor_sync(0xffffffffu, pd, 2);
            if (t4 == 0) {
                atomicAdd(&sred[mloc], ps);
                atomicAdd(&sred[M_TILE + mloc], pd);
            }
        }
    }
    __syncthreads();
    if (t < M_TILE) {
        int node = base + t;
        if (node < N_NODES) {
            g_as2[node] = sred[t];
            g_ad2[node] = sred[M_TILE + t];
        }
    }
}

// ------------------------------------------------------------------
// K5: layer-2 gather over CSR (single head, fp16 h2, L2-resident).
__global__ __launch_bounds__(256) void k_gather2(
    const float* __restrict__ b2, float* __restrict__ out)
{
    int i = blockIdx.x * 8 + (threadIdx.x >> 5);
    if (i >= N_NODES) return;
    int lane = threadIdx.x & 31;

    float adst = g_ad2[i];
    float denom = 0.f;
    float4 acc = make_float4(0.f, 0.f, 0.f, 0.f);

    int beg = g_off[i], end = g_off[i + 1];
    for (int j = beg; j < end; ++j) {
        int src = g_adj[j];
        float tt = g_as2[src] + adst;
        tt = (tt > 0.f) ? tt : 0.2f * tt;
        float p = __expf(tt);
        denom += p;
        uint2 u = *(const uint2*)(g_h2h + (size_t)src * F2 + lane * 4);
        float2 f01 = __half22float2(*(__half2*)&u.x);
        float2 f23 = __half22float2(*(__half2*)&u.y);
        acc.x += p * f01.x; acc.y += p * f01.y;
        acc.z += p * f23.x; acc.w += p * f23.y;
    }

    float inv = 1.f / (denom + 1e-16f);
    float4 bb = *((const float4*)b2 + lane);
    float4 r;
    r.x = fmaxf(acc.x * inv + bb.x, 0.f);
    r.y = fmaxf(acc.y * inv + bb.y, 0.f);
    r.z = fmaxf(acc.z * inv + bb.z, 0.f);
    r.w = fmaxf(acc.w * inv + bb.w, 0.f);
    ((float4*)(out + (size_t)i * F2))[lane] = r;
}

// ------------------------------------------------------------------
extern "C" void kernel_launch(void* const* d_in, const int* in_sizes, int n_in,
                              void* d_out, int out_size)
{
    const float* x   = (const float*)d_in[0];
    const void*  ei  = d_in[1];                 // [2, 300000] (int64 expected)
    const float* W1  = (const float*)d_in[2];
    const float* as1 = (const float*)d_in[3];
    const float* ad1 = (const float*)d_in[4];
    const float* b1  = (const float*)d_in[5];
    const float* W2  = (const float*)d_in[6];
    const float* as2 = (const float*)d_in[7];
    const float* ad2 = (const float*)d_in[8];
    const float* b2  = (const float*)d_in[9];
    float* out = (float*)d_out;

    k_init<<<(N_NODES + 255) / 256, 256>>>((const int*)ei);
    k_count<<<(E_TOT + 255) / 256, 256>>>(ei);
    k_scan<<<1, 1024>>>();
    k_fill<<<(E_TOT + 255) / 256, 256>>>(ei);
    k_prepW2<<<(F1 * F2 + 255) / 256, 256>>>(W2);
    k_reduceW<<<8, 256>>>(W1, as1, ad1);
    k_nodescal<<<(N_NODES * HEADS + 255) / 256, 256>>>(x);
    k_gather1<<<(N_NODES + 7) / 8, 256>>>(x);
    k_fused4<<<(N_NODES + M_TILE - 1) / M_TILE, 256>>>(W1, b1, as2, ad2);
    k_gather2<<<(N_NODES + 7) / 8, 256>>>(b2, out);
}

// round 14
// speedup vs baseline: 1.6006x; 1.6006x over previous
#include <cuda_runtime.h>
#include <cuda_fp16.h>
#include <cstdint>

#define N_NODES 100000
#define E_RAW   300000
#define E_TOT   400000   // raw edges + self loops
#define F1      1024     // heads*hid layer 1
#define HEADS   8
#define F2      128
#define M_TILE  64
#define KC      32       // k chunk for fused GEMM

#define NB_HEAD 391      // blocks for head-init in k_setup1
#define NB_BUILD 1563    // blocks for edge build in k_setup2

// ---- scratch (global __device__ arrays; ~49 MB total) ----
__device__ float  g_xagg[(size_t)N_NODES * 32];  // per-node, per-head weighted x sum (normalized)
__device__ __half g_h2h[(size_t)N_NODES * F2];   // layer-2 features per node, fp16 (25.6 MB)
__device__ __half g_W2h[F2 * F1];                // W2 transposed [n][k], fp16
__device__ float  g_as1[N_NODES * HEADS];
__device__ float  g_ad1[N_NODES * HEADS];
__device__ float  g_as2[N_NODES];
__device__ float  g_ad2[N_NODES];
__device__ int    g_head[N_NODES];               // per-dst linked list head
__device__ int    g_next[E_TOT];                 // linked list next
__device__ int    g_src[E_TOT];                  // decoded int32 src per edge
__device__ float  g_M1s[4 * HEADS];              // W1^T @ a_src  (4 x 8)
__device__ float  g_M1d[4 * HEADS];              // W1^T @ a_dst  (4 x 8)
__device__ int    g_is64;                        // edge_index dtype flag

#define MMA_F16(d, a0, a1, a2, a3, b0, b1) \
    asm volatile("mma.sync.aligned.m16n8k16.row.col.f32.f16.f16.f32 " \
        "{%0,%1,%2,%3}, {%4,%5,%6,%7}, {%8,%9}, {%0,%1,%2,%3};" \
        : "+f"((d)[0]), "+f"((d)[1]), "+f"((d)[2]), "+f"((d)[3]) \
        : "r"(a0), "r"(a1), "r"(a2), "r"(a3), "r"(b0), "r"(b1))

#define LDSM_X4(r, addr) \
    asm volatile("ldmatrix.sync.aligned.m8n8.x4.shared.b16 {%0,%1,%2,%3}, [%4];" \
        : "=r"((r)[0]), "=r"((r)[1]), "=r"((r)[2]), "=r"((r)[3]) : "r"(addr))

// ------------------------------------------------------------------
// K0 (setup1): head-init + dtype detect + reduceW, disjoint block ranges.
__global__ void k_setup1(const int* __restrict__ ei32,
                         const float* __restrict__ W1,
                         const float* __restrict__ as, const float* __restrict__ ad) {
    int b = blockIdx.x;
    int t = threadIdx.x;
    if (b < NB_HEAD) {
        int i = b * 256 + t;
        if (i < N_NODES) g_head[i] = -1;
        if (b == 0) {
            int v = ei32[2 * t + 1];
            int any = __syncthreads_or(v);
            if (t == 0) g_is64 = (any == 0) ? 1 : 0;
        }
        return;
    }
    // reduceW: 8 blocks -> 64 warps -> 64 dot products (M1s then M1d)
    int wid = (b - NB_HEAD) * 8 + (t >> 5);      // 0..63
    int lane = t & 31;
    int idx = wid & 31;
    int d = idx >> 3, h = idx & 7;
    const float* a = (wid < 32) ? as : ad;
    const float* wrow = W1 + d * F1 + h * 128;
    const float* arow = a + h * 128;
    float s = 0.f;
    #pragma unroll
    for (int c = 0; c < 4; ++c) s += wrow[lane + 32 * c] * arow[lane + 32 * c];
    #pragma unroll
    for (int o = 16; o; o >>= 1) s += __shfl_xor_sync(0xffffffffu, s, o);
    if (lane == 0) {
        if (wid < 32) g_M1s[d * 8 + h] = s; else g_M1d[d * 8 + h] = s;
    }
}

// K1 (setup2): linked-list build + W2 fp16 transpose, disjoint block ranges.
__global__ void k_setup2(const void* __restrict__ ei, const float* __restrict__ W2) {
    int b = blockIdx.x;
    int t = threadIdx.x;
    if (b < NB_BUILD) {
        int e = b * 256 + t;
        if (e >= E_TOT) return;
        int is64 = g_is64;
        int src, dst;
        if (e < E_RAW) {
            if (is64) {
                src = (int)((const long long*)ei)[e];
                dst = (int)((const long long*)ei)[E_RAW + e];
            } else {
                src = ((const int*)ei)[e];
                dst = ((const int*)ei)[E_RAW + e];
            }
        } else {
            src = dst = e - E_RAW;
        }
        g_src[e] = src;
        g_next[e] = atomicExch(&g_head[dst], e);
        return;
    }
    // prepW2: (b - NB_BUILD) in [0, 512): convert+transpose W2 -> fp16 [n][k]
    int i = (b - NB_BUILD) * 256 + t;            // i = n*1024 + k
    if (i < F1 * F2) {
        int n = i >> 10, k = i & 1023;
        g_W2h[i] = __float2half(W2[k * F2 + n]);
    }
}

// ------------------------------------------------------------------
// K2: per-node attention scalars: as1[n,h] = sum_d x[n,d] * M1s[d,h]
__global__ __launch_bounds__(256) void k_nodescal(const float* __restrict__ x) {
    int i = blockIdx.x * blockDim.x + threadIdx.x;   // i = n*8 + h
    if (i >= N_NODES * HEADS) return;
    int n = i >> 3, h = i & 7;
    float x0 = x[n * 4 + 0], x1 = x[n * 4 + 1];
    float x2 = x[n * 4 + 2], x3 = x[n * 4 + 3];
    g_as1[i] = x0 * g_M1s[0 * 8 + h] + x1 * g_M1s[1 * 8 + h]
             + x2 * g_M1s[2 * 8 + h] + x3 * g_M1s[3 * 8 + h];
    g_ad1[i] = x0 * g_M1d[0 * 8 + h] + x1 * g_M1d[1 * 8 + h]
             + x2 * g_M1d[2 * 8 + h] + x3 * g_M1d[3 * 8 + h];
}

// ------------------------------------------------------------------
// K3: layer-1 gather in x-space. Warp per dst node. (x, as1 L2-resident)
// Launch index 3 -> this is the kernel ncu captures.
__global__ __launch_bounds__(256) void k_gather1(const float* __restrict__ x) {
    int i = blockIdx.x * 8 + (threadIdx.x >> 5);
    if (i >= N_NODES) return;
    int lane = threadIdx.x & 31;
    int hh = lane >> 2, dd = lane & 3;

    float adst = (lane < 8) ? g_ad1[i * HEADS + lane] : 0.f;
    float acc = 0.f, denom = 0.f;

    int e = (lane == 0) ? g_head[i] : 0;
    for (;;) {
        int ec = __shfl_sync(0xffffffffu, e, 0);
        if (ec < 0) break;
        int src = g_src[ec];
        float pp = 0.f;
        if (lane < 8) {
            float tt = g_as1[src * HEADS + lane] + adst;
            tt = (tt > 0.f) ? tt : 0.2f * tt;        // leaky_relu 0.2
            pp = __expf(tt);
        }
        float p = __shfl_sync(0xffffffffu, pp, hh);
        denom += p;
        acc += p * x[src * 4 + dd];
        if (lane == 0) e = g_next[ec];
    }
    g_xagg[(size_t)i * 32 + lane] = acc / (denom + 1e-16f);
}

// ------------------------------------------------------------------
// K4: fused layer-1 reconstruct + layer-2 GEMM on fp16 tensor cores.
// (frozen R12 structure: single buffer, cp.async sB, ldmatrix fragments)
__global__ __launch_bounds__(256) void k_fused4(
    const float* __restrict__ W1, const float* __restrict__ b1,
    const float* __restrict__ as2, const float* __restrict__ ad2)
{
    __shared__ __align__(16) __half sA[M_TILE * 40];  // [m][kc] pad 40
    __shared__ __align__(16) __half sB[F2 * 40];      // [n][kc] pad 40
    __shared__ __align__(16) float sxa[M_TILE * 33];  // [m][32] pad 33
    __shared__ float sred[2 * M_TILE];

    int t = threadIdx.x;
    int base = blockIdx.x * M_TILE;
    int lane = t & 31, w = t >> 5;
    int mw = w & 1, nw = w >> 1;
    int g = lane >> 2, t4 = lane & 3;

    #pragma unroll
    for (int q = 0; q < 8; ++q) {
        int idx = q * 256 + t;            // 0..2047
        int m = idx >> 5, col = idx & 31;
        float v = (base + m < N_NODES) ? g_xagg[(size_t)(base + m) * 32 + col] : 0.f;
        sxa[m * 33 + col] = v;
    }
    if (t < 2 * M_TILE) sred[t] = 0.f;
    __syncthreads();

    float acc[2][4][4];
    #pragma unroll
    for (int mf = 0; mf < 2; ++mf)
        #pragma unroll
        for (int nf = 0; nf < 4; ++nf)
            #pragma unroll
            for (int q = 0; q < 4; ++q) acc[mf][nf][q] = 0.f;

    int mp = t >> 2;       // producer node 0..63
    int kq = t & 3;        // producer 8-k chunk

    uint32_t sb_dst[2];
    const __half* sb_src[2];
    #pragma unroll
    for (int q = 0; q < 2; ++q) {
        int lin = q * 256 + t;               // 0..511
        int n = lin >> 2, c8 = lin & 3;
        sb_dst[q] = (uint32_t)__cvta_generic_to_shared(&sB[n * 40 + c8 * 8]);
        sb_src[q] = g_W2h + (size_t)n * F1 + c8 * 8;
    }

    uint32_t sAu = (uint32_t)__cvta_generic_to_shared(&sA[0]);
    uint32_t sBu = (uint32_t)__cvta_generic_to_shared(&sB[0]);
    int a_off = ((lane & 7) + ((lane >> 3) & 1) * 8) * 40 + ((lane >> 4) & 1) * 8;
    int b_off = ((lane & 7) + ((lane >> 3) & 2) * 4) * 40 + ((lane >> 3) & 1) * 8;
    uint32_t am0 = sAu + 2u * (a_off + (mw * 32 + 0) * 40);
    uint32_t am1 = sAu + 2u * (a_off + (mw * 32 + 16) * 40);
    uint32_t bn0 = sBu + 2u * (b_off + (nw * 32 + 0) * 40);
    uint32_t bn2 = sBu + 2u * (b_off + (nw * 32 + 16) * 40);

    for (int c = 0; c < F1 / KC; ++c) {          // 32 chunks
        int h = c >> 2;
        int kg = c * KC;
        #pragma unroll
        for (int q = 0; q < 2; ++q) {
            const __half* src = sb_src[q] + kg;
            asm volatile("cp.async.cg.shared.global [%0], [%1], 16;"
                         :: "r"(sb_dst[q]), "l"(src));
        }
        asm volatile("cp.async.commit_group;");

        float xa0 = sxa[mp * 33 + h * 4 + 0], xa1 = sxa[mp * 33 + h * 4 + 1];
        float xa2 = sxa[mp * 33 + h * 4 + 2], xa3 = sxa[mp * 33 + h * 4 + 3];
        float f[8];
        #pragma unroll
        for (int j2 = 0; j2 < 2; ++j2) {
            int kk = kq * 8 + j2 * 4;
            int cg = kg + kk;
            float4 w0 = *(const float4*)(W1 + 0 * F1 + cg);
            float4 w1 = *(const float4*)(W1 + 1 * F1 + cg);
            float4 w2 = *(const float4*)(W1 + 2 * F1 + cg);
            float4 w3 = *(const float4*)(W1 + 3 * F1 + cg);
            float4 bb = *(const float4*)(b1 + cg);
            f[j2 * 4 + 0] = fmaxf(xa0 * w0.x + xa1 * w1.x + xa2 * w2.x + xa3 * w3.x + bb.x, 0.f);
            f[j2 * 4 + 1] = fmaxf(xa0 * w0.y + xa1 * w1.y + xa2 * w2.y + xa3 * w3.y + bb.y, 0.f);
            f[j2 * 4 + 2] = fmaxf(xa0 * w0.z + xa1 * w1.z + xa2 * w2.z + xa3 * w3.z + bb.z, 0.f);
            f[j2 * 4 + 3] = fmaxf(xa0 * w0.w + xa1 * w1.w + xa2 * w2.w + xa3 * w3.w + bb.w, 0.f);
        }
        uint4 v;
        *(__half2*)&v.x = __floats2half2_rn(f[0], f[1]);
        *(__half2*)&v.y = __floats2half2_rn(f[2], f[3]);
        *(__half2*)&v.z = __floats2half2_rn(f[4], f[5]);
        *(__half2*)&v.w = __floats2half2_rn(f[6], f[7]);
        *(uint4*)(&sA[mp * 40 + kq * 8]) = v;

        asm volatile("cp.async.wait_group 0;" ::: "memory");
        __syncthreads();

        #pragma unroll
        for (int ks = 0; ks < 2; ++ks) {
            uint32_t a0[4], a1[4], b0[4], b2[4];
            LDSM_X4(a0, am0 + ks * 32);
            LDSM_X4(a1, am1 + ks * 32);
            LDSM_X4(b0, bn0 + ks * 32);
            LDSM_X4(b2, bn2 + ks * 32);
            MMA_F16(acc[0][0], a0[0], a0[1], a0[2], a0[3], b0[0], b0[1]);
            MMA_F16(acc[0][1], a0[0], a0[1], a0[2], a0[3], b0[2], b0[3]);
            MMA_F16(acc[0][2], a0[0], a0[1], a0[2], a0[3], b2[0], b2[1]);
            MMA_F16(acc[0][3], a0[0], a0[1], a0[2], a0[3], b2[2], b2[3]);
            MMA_F16(acc[1][0], a1[0], a1[1], a1[2], a1[3], b0[0], b0[1]);
            MMA_F16(acc[1][1], a1[0], a1[1], a1[2], a1[3], b0[2], b0[3]);
            MMA_F16(acc[1][2], a1[0], a1[1], a1[2], a1[3], b2[0], b2[1]);
            MMA_F16(acc[1][3], a1[0], a1[1], a1[2], a1[3], b2[2], b2[3]);
        }
        __syncthreads();
    }

    // ---- epilogue: store h2 (fp16) + fused att2 dots ----
    #pragma unroll
    for (int mf = 0; mf < 2; ++mf) {
        #pragma unroll
        for (int half_ = 0; half_ < 2; ++half_) {
            int mloc = mw * 32 + mf * 16 + g + half_ * 8;
            int node = base + mloc;
            float ps = 0.f, pd = 0.f;
            #pragma unroll
            for (int nf = 0; nf < 4; ++nf) {
                int col = nw * 32 + nf * 8 + 2 * t4;
                float c0 = acc[mf][nf][half_ * 2 + 0];
                float c1 = acc[mf][nf][half_ * 2 + 1];
                if (node < N_NODES) {
                    *(__half2*)(g_h2h + (size_t)node * F2 + col) = __floats2half2_rn(c0, c1);
                }
                ps += c0 * as2[col] + c1 * as2[col + 1];
                pd += c0 * ad2[col] + c1 * ad2[col + 1];
            }
            ps += __shfl_xor_sync(0xffffffffu, ps, 1);
            ps += __shfl_xor_sync(0xffffffffu, ps, 2);
            pd += __shfl_xor_sync(0xffffffffu, pd, 1);
            pd += __shfl_xor_sync(0xffffffffu, pd, 2);
            if (t4 == 0) {
                atomicAdd(&sred[mloc], ps);
                atomicAdd(&sred[M_TILE + mloc], pd);
            }
        }
    }
    __syncthreads();
    if (t < M_TILE) {
        int node = base + t;
        if (node < N_NODES) {
            g_as2[node] = sred[t];
            g_ad2[node] = sred[M_TILE + t];
        }
    }
}

// ------------------------------------------------------------------
// K5: layer-2 gather (single head, fp16 h2, L2-resident). Warp per node.
__global__ __launch_bounds__(256) void k_gather2(
    const float* __restrict__ b2, float* __restrict__ out)
{
    int i = blockIdx.x * 8 + (threadIdx.x >> 5);
    if (i >= N_NODES) return;
    int lane = threadIdx.x & 31;

    float adst = g_ad2[i];
    float denom = 0.f;
    float4 acc = make_float4(0.f, 0.f, 0.f, 0.f);

    int e = (lane == 0) ? g_head[i] : 0;
    for (;;) {
        int ec = __shfl_sync(0xffffffffu, e, 0);
        if (ec < 0) break;
        int src = g_src[ec];
        float tt = g_as2[src] + adst;
        tt = (tt > 0.f) ? tt : 0.2f * tt;
        float p = __expf(tt);
        denom += p;
        uint2 u = *(const uint2*)(g_h2h + (size_t)src * F2 + lane * 4);
        float2 f01 = __half22float2(*(__half2*)&u.x);
        float2 f23 = __half22float2(*(__half2*)&u.y);
        acc.x += p * f01.x; acc.y += p * f01.y;
        acc.z += p * f23.x; acc.w += p * f23.y;
        if (lane == 0) e = g_next[ec];
    }

    float inv = 1.f / (denom + 1e-16f);
    float4 bb = *((const float4*)b2 + lane);
    float4 r;
    r.x = fmaxf(acc.x * inv + bb.x, 0.f);
    r.y = fmaxf(acc.y * inv + bb.y, 0.f);
    r.z = fmaxf(acc.z * inv + bb.z, 0.f);
    r.w = fmaxf(acc.w * inv + bb.w, 0.f);
    ((float4*)(out + (size_t)i * F2))[lane] = r;
}

// ------------------------------------------------------------------
extern "C" void kernel_launch(void* const* d_in, const int* in_sizes, int n_in,
                              void* d_out, int out_size)
{
    const float* x   = (const float*)d_in[0];
    const void*  ei  = d_in[1];                 // [2, 300000] (int64 expected)
    const float* W1  = (const float*)d_in[2];
    const float* as1 = (const float*)d_in[3];
    const float* ad1 = (const float*)d_in[4];
    const float* b1  = (const float*)d_in[5];
    const float* W2  = (const float*)d_in[6];
    const float* as2 = (const float*)d_in[7];
    const float* ad2 = (const float*)d_in[8];
    const float* b2  = (const float*)d_in[9];
    float* out = (float*)d_out;

    k_setup1<<<NB_HEAD + 8, 256>>>((const int*)ei, W1, as1, ad1);      // idx 0
    k_setup2<<<NB_BUILD + 512, 256>>>(ei, W2);                         // idx 1
    k_nodescal<<<(N_NODES * HEADS + 255) / 256, 256>>>(x);             // idx 2
    k_gather1<<<(N_NODES + 7) / 8, 256>>>(x);                          // idx 3 (profiled)
    k_fused4<<<(N_NODES + M_TILE - 1) / M_TILE, 256>>>(W1, b1, as2, ad2); // idx 4
    k_gather2<<<(N_NODES + 7) / 8, 256>>>(b2, out);                    // idx 5
}

// round 15
// speedup vs baseline: 1.7704x; 1.1061x over previous
#include <cuda_runtime.h>
#include <cuda_fp16.h>
#include <cstdint>

#define N_NODES 100000
#define E_RAW   300000
#define E_TOT   400000   // raw edges + self loops
#define F1      1024     // heads*hid layer 1
#define HEADS   8
#define F2      128
#define M_TILE  64
#define KC      32       // k chunk for fused GEMM

#define NB_HEAD 391      // blocks for head-init in k_setup1
#define NB_BUILD 1563    // blocks for edge build in k_setup2

// ---- scratch (global __device__ arrays; ~49 MB total) ----
__device__ float  g_xagg[(size_t)N_NODES * 32];  // per-node, per-head weighted x sum (normalized)
__device__ __half g_h2h[(size_t)N_NODES * F2];   // layer-2 features per node, fp16 (25.6 MB)
__device__ __half g_W2h[F2 * F1];                // W2 transposed [n][k], fp16
__device__ float  g_as1[N_NODES * HEADS];
__device__ float  g_ad1[N_NODES * HEADS];
__device__ float  g_as2[N_NODES];
__device__ float  g_ad2[N_NODES];
__device__ int    g_head[N_NODES];               // per-dst linked list head
__device__ int    g_next[E_TOT];                 // linked list next
__device__ int    g_src[E_TOT];                  // decoded int32 src per edge
__device__ float  g_M1s[4 * HEADS];              // W1^T @ a_src  (4 x 8)
__device__ float  g_M1d[4 * HEADS];              // W1^T @ a_dst  (4 x 8)
__device__ int    g_is64;                        // edge_index dtype flag

#define MMA_F16(d, a0, a1, a2, a3, b0, b1) \
    asm volatile("mma.sync.aligned.m16n8k16.row.col.f32.f16.f16.f32 " \
        "{%0,%1,%2,%3}, {%4,%5,%6,%7}, {%8,%9}, {%0,%1,%2,%3};" \
        : "+f"((d)[0]), "+f"((d)[1]), "+f"((d)[2]), "+f"((d)[3]) \
        : "r"(a0), "r"(a1), "r"(a2), "r"(a3), "r"(b0), "r"(b1))

#define LDSM_X4(r, addr) \
    asm volatile("ldmatrix.sync.aligned.m8n8.x4.shared.b16 {%0,%1,%2,%3}, [%4];" \
        : "=r"((r)[0]), "=r"((r)[1]), "=r"((r)[2]), "=r"((r)[3]) : "r"(addr))

// ------------------------------------------------------------------
// K0 (setup1): head-init + dtype detect + reduceW, disjoint block ranges.
__global__ void k_setup1(const int* __restrict__ ei32,
                         const float* __restrict__ W1,
                         const float* __restrict__ as, const float* __restrict__ ad) {
    int b = blockIdx.x;
    int t = threadIdx.x;
    if (b < NB_HEAD) {
        int i = b * 256 + t;
        if (i < N_NODES) g_head[i] = -1;
        if (b == 0) {
            int v = ei32[2 * t + 1];
            int any = __syncthreads_or(v);
            if (t == 0) g_is64 = (any == 0) ? 1 : 0;
        }
        return;
    }
    int wid = (b - NB_HEAD) * 8 + (t >> 5);      // 0..63
    int lane = t & 31;
    int idx = wid & 31;
    int d = idx >> 3, h = idx & 7;
    const float* a = (wid < 32) ? as : ad;
    const float* wrow = W1 + d * F1 + h * 128;
    const float* arow = a + h * 128;
    float s = 0.f;
    #pragma unroll
    for (int c = 0; c < 4; ++c) s += wrow[lane + 32 * c] * arow[lane + 32 * c];
    #pragma unroll
    for (int o = 16; o; o >>= 1) s += __shfl_xor_sync(0xffffffffu, s, o);
    if (lane == 0) {
        if (wid < 32) g_M1s[d * 8 + h] = s; else g_M1d[d * 8 + h] = s;
    }
}

// K1 (setup2): linked-list build + W2 fp16 transpose, disjoint block ranges.
__global__ void k_setup2(const void* __restrict__ ei, const float* __restrict__ W2) {
    int b = blockIdx.x;
    int t = threadIdx.x;
    if (b < NB_BUILD) {
        int e = b * 256 + t;
        if (e >= E_TOT) return;
        int is64 = g_is64;
        int src, dst;
        if (e < E_RAW) {
            if (is64) {
                src = (int)((const long long*)ei)[e];
                dst = (int)((const long long*)ei)[E_RAW + e];
            } else {
                src = ((const int*)ei)[e];
                dst = ((const int*)ei)[E_RAW + e];
            }
        } else {
            src = dst = e - E_RAW;
        }
        g_src[e] = src;
        g_next[e] = atomicExch(&g_head[dst], e);
        return;
    }
    int i = (b - NB_BUILD) * 256 + t;            // i = n*1024 + k
    if (i < F1 * F2) {
        int n = i >> 10, k = i & 1023;
        g_W2h[i] = __float2half(W2[k * F2 + n]);
    }
}

// ------------------------------------------------------------------
// K2: per-node attention scalars: as1[n,h] = sum_d x[n,d] * M1s[d,h]
__global__ __launch_bounds__(256) void k_nodescal(const float* __restrict__ x) {
    int i = blockIdx.x * blockDim.x + threadIdx.x;   // i = n*8 + h
    if (i >= N_NODES * HEADS) return;
    int n = i >> 3, h = i & 7;
    float x0 = x[n * 4 + 0], x1 = x[n * 4 + 1];
    float x2 = x[n * 4 + 2], x3 = x[n * 4 + 3];
    g_as1[i] = x0 * g_M1s[0 * 8 + h] + x1 * g_M1s[1 * 8 + h]
             + x2 * g_M1s[2 * 8 + h] + x3 * g_M1s[3 * 8 + h];
    g_ad1[i] = x0 * g_M1d[0 * 8 + h] + x1 * g_M1d[1 * 8 + h]
             + x2 * g_M1d[2 * 8 + h] + x3 * g_M1d[3 * 8 + h];
}

// ------------------------------------------------------------------
// K3: layer-1 gather, 4 nodes per warp (8 lanes/node, lane = head).
// Each lane owns head h: its exp, denom, and float4 x accumulator.
// Launch index 3 -> profiled kernel.
__global__ __launch_bounds__(256) void k_gather1(const float* __restrict__ x) {
    int t = threadIdx.x;
    int lane = t & 31;
    int grp = lane >> 3;                  // group within warp: 0..3
    int h = lane & 7;                     // head
    int i = blockIdx.x * 32 + (t >> 5) * 4 + grp;   // 100000 = 3125*32 exact
    unsigned mask = 0xFFu << (grp * 8);
    int lead = grp * 8;

    float adst = g_ad1[i * HEADS + h];
    float4 acc = make_float4(0.f, 0.f, 0.f, 0.f);
    float denom = 0.f;

    int e = (h == 0) ? g_head[i] : 0;
    for (;;) {
        int ec = __shfl_sync(mask, e, lead);
        if (ec < 0) break;
        int src = g_src[ec];
        float tt = g_as1[src * HEADS + h] + adst;
        tt = (tt > 0.f) ? tt : 0.2f * tt;           // leaky_relu 0.2
        float p = __expf(tt);
        denom += p;
        float4 xs = *(const float4*)(x + src * 4);  // 16B broadcast within group
        acc.x += p * xs.x; acc.y += p * xs.y;
        acc.z += p * xs.z; acc.w += p * xs.w;
        if (h == 0) e = g_next[ec];
    }
    float inv = 1.f / (denom + 1e-16f);
    float4 r;
    r.x = acc.x * inv; r.y = acc.y * inv; r.z = acc.z * inv; r.w = acc.w * inv;
    *(float4*)(g_xagg + (size_t)i * 32 + h * 4) = r;   // layout [head][dim]
}

// ------------------------------------------------------------------
// K4: fused layer-1 reconstruct + layer-2 GEMM on fp16 tensor cores.
// (frozen R12 structure: single buffer, cp.async sB, ldmatrix fragments)
__global__ __launch_bounds__(256) void k_fused4(
    const float* __restrict__ W1, const float* __restrict__ b1,
    const float* __restrict__ as2, const float* __restrict__ ad2)
{
    __shared__ __align__(16) __half sA[M_TILE * 40];  // [m][kc] pad 40
    __shared__ __align__(16) __half sB[F2 * 40];      // [n][kc] pad 40
    __shared__ __align__(16) float sxa[M_TILE * 33];  // [m][32] pad 33
    __shared__ float sred[2 * M_TILE];

    int t = threadIdx.x;
    int base = blockIdx.x * M_TILE;
    int lane = t & 31, w = t >> 5;
    int mw = w & 1, nw = w >> 1;
    int g = lane >> 2, t4 = lane & 3;

    #pragma unroll
    for (int q = 0; q < 8; ++q) {
        int idx = q * 256 + t;            // 0..2047
        int m = idx >> 5, col = idx & 31;
        float v = (base + m < N_NODES) ? g_xagg[(size_t)(base + m) * 32 + col] : 0.f;
        sxa[m * 33 + col] = v;
    }
    if (t < 2 * M_TILE) sred[t] = 0.f;
    __syncthreads();

    float acc[2][4][4];
    #pragma unroll
    for (int mf = 0; mf < 2; ++mf)
        #pragma unroll
        for (int nf = 0; nf < 4; ++nf)
            #pragma unroll
            for (int q = 0; q < 4; ++q) acc[mf][nf][q] = 0.f;

    int mp = t >> 2;       // producer node 0..63
    int kq = t & 3;        // producer 8-k chunk

    uint32_t sb_dst[2];
    const __half* sb_src[2];
    #pragma unroll
    for (int q = 0; q < 2; ++q) {
        int lin = q * 256 + t;               // 0..511
        int n = lin >> 2, c8 = lin & 3;
        sb_dst[q] = (uint32_t)__cvta_generic_to_shared(&sB[n * 40 + c8 * 8]);
        sb_src[q] = g_W2h + (size_t)n * F1 + c8 * 8;
    }

    uint32_t sAu = (uint32_t)__cvta_generic_to_shared(&sA[0]);
    uint32_t sBu = (uint32_t)__cvta_generic_to_shared(&sB[0]);
    int a_off = ((lane & 7) + ((lane >> 3) & 1) * 8) * 40 + ((lane >> 4) & 1) * 8;
    int b_off = ((lane & 7) + ((lane >> 3) & 2) * 4) * 40 + ((lane >> 3) & 1) * 8;
    uint32_t am0 = sAu + 2u * (a_off + (mw * 32 + 0) * 40);
    uint32_t am1 = sAu + 2u * (a_off + (mw * 32 + 16) * 40);
    uint32_t bn0 = sBu + 2u * (b_off + (nw * 32 + 0) * 40);
    uint32_t bn2 = sBu + 2u * (b_off + (nw * 32 + 16) * 40);

    for (int c = 0; c < F1 / KC; ++c) {          // 32 chunks
        int h = c >> 2;
        int kg = c * KC;
        #pragma unroll
        for (int q = 0; q < 2; ++q) {
            const __half* src = sb_src[q] + kg;
            asm volatile("cp.async.cg.shared.global [%0], [%1], 16;"
                         :: "r"(sb_dst[q]), "l"(src));
        }
        asm volatile("cp.async.commit_group;");

        float xa0 = sxa[mp * 33 + h * 4 + 0], xa1 = sxa[mp * 33 + h * 4 + 1];
        float xa2 = sxa[mp * 33 + h * 4 + 2], xa3 = sxa[mp * 33 + h * 4 + 3];
        float f[8];
        #pragma unroll
        for (int j2 = 0; j2 < 2; ++j2) {
            int kk = kq * 8 + j2 * 4;
            int cg = kg + kk;
            float4 w0 = *(const float4*)(W1 + 0 * F1 + cg);
            float4 w1 = *(const float4*)(W1 + 1 * F1 + cg);
            float4 w2 = *(const float4*)(W1 + 2 * F1 + cg);
            float4 w3 = *(const float4*)(W1 + 3 * F1 + cg);
            float4 bb = *(const float4*)(b1 + cg);
            f[j2 * 4 + 0] = fmaxf(xa0 * w0.x + xa1 * w1.x + xa2 * w2.x + xa3 * w3.x + bb.x, 0.f);
            f[j2 * 4 + 1] = fmaxf(xa0 * w0.y + xa1 * w1.y + xa2 * w2.y + xa3 * w3.y + bb.y, 0.f);
            f[j2 * 4 + 2] = fmaxf(xa0 * w0.z + xa1 * w1.z + xa2 * w2.z + xa3 * w3.z + bb.z, 0.f);
            f[j2 * 4 + 3] = fmaxf(xa0 * w0.w + xa1 * w1.w + xa2 * w2.w + xa3 * w3.w + bb.w, 0.f);
        }
        uint4 v;
        *(__half2*)&v.x = __floats2half2_rn(f[0], f[1]);
        *(__half2*)&v.y = __floats2half2_rn(f[2], f[3]);
        *(__half2*)&v.z = __floats2half2_rn(f[4], f[5]);
        *(__half2*)&v.w = __floats2half2_rn(f[6], f[7]);
        *(uint4*)(&sA[mp * 40 + kq * 8]) = v;

        asm volatile("cp.async.wait_group 0;" ::: "memory");
        __syncthreads();

        #pragma unroll
        for (int ks = 0; ks < 2; ++ks) {
            uint32_t a0[4], a1[4], b0[4], b2[4];
            LDSM_X4(a0, am0 + ks * 32);
            LDSM_X4(a1, am1 + ks * 32);
            LDSM_X4(b0, bn0 + ks * 32);
            LDSM_X4(b2, bn2 + ks * 32);
            MMA_F16(acc[0][0], a0[0], a0[1], a0[2], a0[3], b0[0], b0[1]);
            MMA_F16(acc[0][1], a0[0], a0[1], a0[2], a0[3], b0[2], b0[3]);
            MMA_F16(acc[0][2], a0[0], a0[1], a0[2], a0[3], b2[0], b2[1]);
            MMA_F16(acc[0][3], a0[0], a0[1], a0[2], a0[3], b2[2], b2[3]);
            MMA_F16(acc[1][0], a1[0], a1[1], a1[2], a1[3], b0[0], b0[1]);
            MMA_F16(acc[1][1], a1[0], a1[1], a1[2], a1[3], b0[2], b0[3]);
            MMA_F16(acc[1][2], a1[0], a1[1], a1[2], a1[3], b2[0], b2[1]);
            MMA_F16(acc[1][3], a1[0], a1[1], a1[2], a1[3], b2[2], b2[3]);
        }
        __syncthreads();
    }

    // ---- epilogue: store h2 (fp16) + fused att2 dots ----
    #pragma unroll
    for (int mf = 0; mf < 2; ++mf) {
        #pragma unroll
        for (int half_ = 0; half_ < 2; ++half_) {
            int mloc = mw * 32 + mf * 16 + g + half_ * 8;
            int node = base + mloc;
            float ps = 0.f, pd = 0.f;
            #pragma unroll
            for (int nf = 0; nf < 4; ++nf) {
                int col = nw * 32 + nf * 8 + 2 * t4;
                float c0 = acc[mf][nf][half_ * 2 + 0];
                float c1 = acc[mf][nf][half_ * 2 + 1];
                if (node < N_NODES) {
                    *(__half2*)(g_h2h + (size_t)node * F2 + col) = __floats2half2_rn(c0, c1);
                }
                ps += c0 * as2[col] + c1 * as2[col + 1];
                pd += c0 * ad2[col] + c1 * ad2[col + 1];
            }
            ps += __shfl_xor_sync(0xffffffffu, ps, 1);
            ps += __shfl_xor_sync(0xffffffffu, ps, 2);
            pd += __shfl_xor_sync(0xffffffffu, pd, 1);
            pd += __shfl_xor_sync(0xffffffffu, pd, 2);
            if (t4 == 0) {
                atomicAdd(&sred[mloc], ps);
                atomicAdd(&sred[M_TILE + mloc], pd);
            }
        }
    }
    __syncthreads();
    if (t < M_TILE) {
        int node = base + t;
        if (node < N_NODES) {
            g_as2[node] = sred[t];
            g_ad2[node] = sred[M_TILE + t];
        }
    }
}

// ------------------------------------------------------------------
// K5: layer-2 gather, 2 nodes per warp (16 lanes/node, uint4 = 8 ch/lane).
__global__ __launch_bounds__(256) void k_gather2(
    const float* __restrict__ b2, float* __restrict__ out)
{
    int t = threadIdx.x;
    int lane = t & 31;
    int half_ = lane >> 4;                // node within warp: 0/1
    int sl = lane & 15;                   // sub-lane: channels sl*8..sl*8+7
    int i = blockIdx.x * 16 + (t >> 5) * 2 + half_;   // 100000 = 6250*16 exact
    unsigned mask = 0xFFFFu << (half_ * 16);
    int lead = half_ * 16;

    float adst = g_ad2[i];
    float denom = 0.f;
    float2 a0 = {0.f, 0.f}, a1 = {0.f, 0.f}, a2 = {0.f, 0.f}, a3 = {0.f, 0.f};

    int e = (sl == 0) ? g_head[i] : 0;
    for (;;) {
        int ec = __shfl_sync(mask, e, lead);
        if (ec < 0) break;
        int src = g_src[ec];
        float tt = g_as2[src] + adst;
        tt = (tt > 0.f) ? tt : 0.2f * tt;
        float p = __expf(tt);
        denom += p;
        uint4 u = *(const uint4*)(g_h2h + (size_t)src * F2 + sl * 8);
        float2 f0 = __half22float2(*(__half2*)&u.x);
        float2 f1 = __half22float2(*(__half2*)&u.y);
        float2 f2v = __half22float2(*(__half2*)&u.z);
        float2 f3 = __half22float2(*(__half2*)&u.w);
        a0.x += p * f0.x;  a0.y += p * f0.y;
        a1.x += p * f1.x;  a1.y += p * f1.y;
        a2.x += p * f2v.x; a2.y += p * f2v.y;
        a3.x += p * f3.x;  a3.y += p * f3.y;
        if (sl == 0) e = g_next[ec];
    }

    float inv = 1.f / (denom + 1e-16f);
    float4 bb0 = *((const float4*)b2 + sl * 2);
    float4 bb1 = *((const float4*)b2 + sl * 2 + 1);
    float4 r0, r1;
    r0.x = fmaxf(a0.x * inv + bb0.x, 0.f);
    r0.y = fmaxf(a0.y * inv + bb0.y, 0.f);
    r0.z = fmaxf(a1.x * inv + bb0.z, 0.f);
    r0.w = fmaxf(a1.y * inv + bb0.w, 0.f);
    r1.x = fmaxf(a2.x * inv + bb1.x, 0.f);
    r1.y = fmaxf(a2.y * inv + bb1.y, 0.f);
    r1.z = fmaxf(a3.x * inv + bb1.z, 0.f);
    r1.w = fmaxf(a3.y * inv + bb1.w, 0.f);
    float4* orow = (float4*)(out + (size_t)i * F2);
    orow[sl * 2] = r0;
    orow[sl * 2 + 1] = r1;
}

// ------------------------------------------------------------------
extern "C" void kernel_launch(void* const* d_in, const int* in_sizes, int n_in,
                              void* d_out, int out_size)
{
    const float* x   = (const float*)d_in[0];
    const void*  ei  = d_in[1];                 // [2, 300000] (int64 expected)
    const float* W1  = (const float*)d_in[2];
    const float* as1 = (const float*)d_in[3];
    const float* ad1 = (const float*)d_in[4];
    const float* b1  = (const float*)d_in[5];
    const float* W2  = (const float*)d_in[6];
    const float* as2 = (const float*)d_in[7];
    const float* ad2 = (const float*)d_in[8];
    const float* b2  = (const float*)d_in[9];
    float* out = (float*)d_out;

    k_setup1<<<NB_HEAD + 8, 256>>>((const int*)ei, W1, as1, ad1);      // idx 0
    k_setup2<<<NB_BUILD + 512, 256>>>(ei, W2);                         // idx 1
    k_nodescal<<<(N_NODES * HEADS + 255) / 256, 256>>>(x);             // idx 2
    k_gather1<<<N_NODES / 32, 256>>>(x);                               // idx 3 (profiled)
    k_fused4<<<(N_NODES + M_TILE - 1) / M_TILE, 256>>>(W1, b1, as2, ad2); // idx 4
    k_gather2<<<N_NODES / 16, 256>>>(b2, out);                         // idx 5
}